// round 1
// baseline (speedup 1.0000x reference)
#include <cuda_runtime.h>
#include <math.h>

// ===================== problem constants =====================
namespace {
constexpr int Bz  = 8;
constexpr int S   = 2048;
constexpr int D   = 128;
constexpr int DV  = 128;
constexpr int CHUNKS = 16;             // k-chunks per batch for K^T V
constexpr int CROWS  = S / CHUNKS;     // 128 rows per chunk
constexpr int KT     = 8;              // rows staged per iteration
constexpr int NSTAGE = CROWS / KT;     // 16 stages
}

// Scratch for M = K^T V per batch: [Bz][D][DV] fp32 (512 KB)
__device__ float g_M[Bz * D * DV];

// ===================== packed f32x2 helpers =====================
__device__ __forceinline__ unsigned long long pk2(float lo, float hi) {
    unsigned long long r;
    asm("mov.b64 %0, {%1, %2};" : "=l"(r) : "f"(lo), "f"(hi));
    return r;
}
__device__ __forceinline__ void fma2(unsigned long long& d,
                                     unsigned long long a,
                                     unsigned long long b) {
    asm("fma.rn.f32x2 %0, %1, %2, %0;" : "+l"(d) : "l"(a), "l"(b));
}
__device__ __forceinline__ float2 unpk2(unsigned long long v) {
    float lo, hi;
    asm("mov.b64 {%0, %1}, %2;" : "=f"(lo), "=f"(hi) : "l"(v));
    return make_float2(lo, hi);
}

// ===================== kernel 0: zero scratch =====================
__global__ void zero_m_kernel() {
    int i = blockIdx.x * blockDim.x + threadIdx.x;
    g_M[i] = 0.0f;
}

// ===================== kernel 1: M[b] += chunk of K^T V =====================
// grid = Bz*CHUNKS blocks, 256 threads. Each block: 128 k-rows -> full
// [128 x 128] partial outer-product sum, accumulated in registers
// (thread tile 8 d-rows x 8 v-cols, v packed as 4 f32x2), then atomicAdd.
__global__ void __launch_bounds__(256, 1)
ktv_kernel(const float* __restrict__ Kp, const float* __restrict__ Vp) {
    __shared__ float Ks[2][KT][D];
    __shared__ float Vs[2][KT][DV];

    const int b   = blockIdx.x / CHUNKS;
    const int c   = blockIdx.x % CHUNKS;
    const int tid = threadIdx.x;
    const int ty  = tid >> 4;   // 0..15 -> d rows [ty*8, ty*8+8)
    const int tx  = tid & 15;   // 0..15 -> v cols [tx*8, tx*8+8)

    const float* Kb = Kp + ((size_t)(b * S + c * CROWS)) * D;
    const float* Vb = Vp + ((size_t)(b * S + c * CROWS)) * DV;

    // loader: 256 threads cover 8 rows x 128 floats (one float4 each)
    const int lrow = tid >> 5;         // 0..7
    const int lcol = (tid & 31) * 4;   // 0..124

    unsigned long long acc[8][4];
#pragma unroll
    for (int i = 0; i < 8; ++i)
#pragma unroll
        for (int j = 0; j < 4; ++j) acc[i][j] = 0ull;

    // prologue: stage 0
    {
        float4 kf = *(const float4*)(Kb + lrow * D + lcol);
        float4 vf = *(const float4*)(Vb + lrow * DV + lcol);
        *(float4*)&Ks[0][lrow][lcol] = kf;
        *(float4*)&Vs[0][lrow][lcol] = vf;
    }
    __syncthreads();

    for (int s = 0; s < NSTAGE; ++s) {
        const int cur = s & 1;
        float4 knext, vnext;
        const bool more = (s + 1 < NSTAGE);
        if (more) {
            knext = *(const float4*)(Kb + ((s + 1) * KT + lrow) * D + lcol);
            vnext = *(const float4*)(Vb + ((s + 1) * KT + lrow) * DV + lcol);
        }
#pragma unroll
        for (int r = 0; r < KT; ++r) {
            float4 ka  = *(const float4*)&Ks[cur][r][ty * 8];
            float4 kb4 = *(const float4*)&Ks[cur][r][ty * 8 + 4];
            float4 va  = *(const float4*)&Vs[cur][r][tx * 8];
            float4 vb4 = *(const float4*)&Vs[cur][r][tx * 8 + 4];
            unsigned long long v2[4] = { pk2(va.x, va.y),  pk2(va.z, va.w),
                                         pk2(vb4.x, vb4.y), pk2(vb4.z, vb4.w) };
            float kk[8] = {ka.x, ka.y, ka.z, ka.w, kb4.x, kb4.y, kb4.z, kb4.w};
#pragma unroll
            for (int i = 0; i < 8; ++i) {
                unsigned long long kd = pk2(kk[i], kk[i]);
#pragma unroll
                for (int j = 0; j < 4; ++j) fma2(acc[i][j], kd, v2[j]);
            }
        }
        if (more) {
            const int nxt = cur ^ 1;
            *(float4*)&Ks[nxt][lrow][lcol] = knext;
            *(float4*)&Vs[nxt][lrow][lcol] = vnext;
        }
        __syncthreads();
    }

    float* Mb = g_M + b * D * DV;
#pragma unroll
    for (int i = 0; i < 8; ++i) {
        const int drow = ty * 8 + i;
#pragma unroll
        for (int j = 0; j < 4; ++j) {
            float2 f = unpk2(acc[i][j]);
            atomicAdd(&Mb[drow * DV + tx * 8 + 2 * j],     f.x);
            atomicAdd(&Mb[drow * DV + tx * 8 + 2 * j + 1], f.y);
        }
    }
}

// ===================== kernel 2: O[b] = Q[b] @ M[b] * inv =====================
// grid = Bz * (S/128) blocks, 256 threads. M resident in shared (64 KB),
// Q staged transposed in 8-column stages with register double buffering.
__global__ void __launch_bounds__(256, 1)
qm_kernel(const float* __restrict__ Qp, const float* __restrict__ sfp,
          float* __restrict__ Op) {
    extern __shared__ float sh[];
    float* Ms = sh;              // [D][DV]
    float* Qs = sh + D * DV;     // [2][8][128] transposed stages

    const int nq  = S / 128;     // 16 q-tiles per batch
    const int b   = blockIdx.x / nq;
    const int qt  = blockIdx.x % nq;
    const int tid = threadIdx.x;
    const int ty  = tid >> 4;
    const int tx  = tid & 15;

    const float* Qb = Qp + ((size_t)(b * S + qt * 128)) * D;

    // load full M tile into shared (16384 floats, 16 float4 per thread)
    const float* Mb = g_M + b * D * DV;
#pragma unroll
    for (int k = 0; k < (D * DV) / (256 * 4); ++k) {
        const int idx = (k * 256 + tid) * 4;
        *(float4*)&Ms[idx] = *(const float4*)&Mb[idx];
    }

    // Q stage loader: thread -> (row = tid>>1, 4-col half = (tid&1)*4)
    const int qrow  = tid >> 1;
    const int qhalf = (tid & 1) * 4;

    unsigned long long acc[8][4];
#pragma unroll
    for (int i = 0; i < 8; ++i)
#pragma unroll
        for (int j = 0; j < 4; ++j) acc[i][j] = 0ull;

    // prologue: stage 0 (d cols 0..7), stored transposed Qs[dd][row]
    {
        float4 q0 = *(const float4*)(Qb + qrow * D + qhalf);
        float qv[4] = {q0.x, q0.y, q0.z, q0.w};
#pragma unroll
        for (int k = 0; k < 4; ++k) Qs[(qhalf + k) * 128 + qrow] = qv[k];
    }
    __syncthreads();

    const int NST = D / 8;   // 16 stages
    for (int s = 0; s < NST; ++s) {
        const int cur = s & 1;
        float4 qn;
        const bool more = (s + 1 < NST);
        if (more) qn = *(const float4*)(Qb + qrow * D + (s + 1) * 8 + qhalf);

        const float* Qc = Qs + cur * 1024;
#pragma unroll
        for (int dd = 0; dd < 8; ++dd) {
            const int d = s * 8 + dd;
            float4 qa  = *(const float4*)&Qc[dd * 128 + ty * 8];
            float4 qb4 = *(const float4*)&Qc[dd * 128 + ty * 8 + 4];
            float4 ma  = *(const float4*)&Ms[d * DV + tx * 8];
            float4 mb4 = *(const float4*)&Ms[d * DV + tx * 8 + 4];
            unsigned long long m2[4] = { pk2(ma.x, ma.y),  pk2(ma.z, ma.w),
                                         pk2(mb4.x, mb4.y), pk2(mb4.z, mb4.w) };
            float qq[8] = {qa.x, qa.y, qa.z, qa.w, qb4.x, qb4.y, qb4.z, qb4.w};
#pragma unroll
            for (int i = 0; i < 8; ++i) {
                unsigned long long qd = pk2(qq[i], qq[i]);
#pragma unroll
                for (int j = 0; j < 4; ++j) fma2(acc[i][j], qd, m2[j]);
            }
        }
        if (more) {
            float* Qn = Qs + (cur ^ 1) * 1024;
            float qv[4] = {qn.x, qn.y, qn.z, qn.w};
#pragma unroll
            for (int k = 0; k < 4; ++k) Qn[(qhalf + k) * 128 + qrow] = qv[k];
        }
        __syncthreads();
    }

    const float sf  = sfp[0];
    const float inv = 1.0f / (sqrtf((float)D) * sf);
    float* Ob = Op + ((size_t)(b * S + qt * 128)) * DV;
#pragma unroll
    for (int i = 0; i < 8; ++i) {
        const int r = ty * 8 + i;
#pragma unroll
        for (int j = 0; j < 4; ++j) {
            float2 f = unpk2(acc[i][j]);
            f.x *= inv;
            f.y *= inv;
            *(float2*)&Ob[r * DV + tx * 8 + 2 * j] = f;
        }
    }
}

// ===================== launch =====================
extern "C" void kernel_launch(void* const* d_in, const int* in_sizes, int n_in,
                              void* d_out, int out_size) {
    // metadata order: qk (unused), qk_scaling_factor, query, key, value
    const float* sf = (const float*)d_in[1];
    const float* Q  = (const float*)d_in[2];
    const float* K  = (const float*)d_in[3];
    const float* V  = (const float*)d_in[4];
    float* O        = (float*)d_out;

    // 0) zero scratch M (Bz*D*DV = 131072 elements)
    zero_m_kernel<<<Bz * D * DV / 256, 256>>>();

    // 1) M[b] = K[b]^T V[b]  (atomic reduction over 16 chunks per batch)
    ktv_kernel<<<Bz * CHUNKS, 256>>>(K, V);

    // 2) O[b] = Q[b] M[b] / (sqrt(D) * sf)
    const int smem_b = (D * DV + 2 * 8 * 128) * (int)sizeof(float);  // 72 KB
    cudaFuncSetAttribute(qm_kernel, cudaFuncAttributeMaxDynamicSharedMemorySize,
                         smem_b);
    qm_kernel<<<Bz * (S / 128), 256, smem_b>>>(Q, sf, O);
}